// round 15
// baseline (speedup 1.0000x reference)
#include <cuda_runtime.h>
#include <cstdint>

// out[n,o,s] = sum_k din[j,k] * W[o,k] + b[o],  j = n*6+s, K=96 (k = 3c+tap)
// mma.sync.m16n8k8.row.col.f32.tf32.tf32.f32 (plain PTX, compute_103-safe).
//
// Persistent producer/consumer pipeline, 96-row tiles, double-buffered A:
//   warps 0-2  : consumers (2 mtiles x 4 ntiles each) + epilogue scatter
//   warps 3-5  : d-producers   warps 6-11 : x-producers
// Producers stage tile t+1 into buf[1-p] while consumers compute tile t from buf[p].
// All staging addresses advance by constant deltas (grid stride + ±ABUF toggle).
// A fragment layout / swizzle / tf32 identical to R10 (rel_err bit-identical).

#define ROWS 96
#define THREADS 384
#define ABUF 36864
#define B_OFF (2 * ABUF)
#define B_BYTES 12288
#define SMEM_TOTAL (B_OFF + B_BYTES)   // 86016 -> 2 CTAs/SM
#define EPI_STRIDE 200
#define NCTA 296

__device__ __align__(16) float WF_g[3072];

__global__ void prep_WF(const float* __restrict__ W) {
    int t = blockIdx.x * blockDim.x + threadIdx.x;
    if (t < 3072) {
        int o = t / 96, k = t - 96 * o;
        int c = k / 3, tap = k - 3 * c;
        int kt, tc;
        if (tap < 2) { kt = c >> 2;       tc = (c & 3) + 4 * tap; }
        else         { kt = 8 + (c >> 3); tc = c & 7; }
        uint32_t v;
        asm("cvt.rna.tf32.f32 %0, %1;" : "=r"(v) : "f"(W[t]));
        int word = (kt * 4 + (o >> 3)) * 64 + ((o & 7) * 4 + (tc & 3)) * 2 + (tc >> 2);
        WF_g[word] = __uint_as_float(v);
    }
}

static __device__ __forceinline__ uint32_t smem_u32(const void* p) {
    uint32_t a;
    asm("{ .reg .u64 t; cvta.to.shared.u64 t, %1; cvt.u32.u64 %0, t; }" : "=r"(a) : "l"(p));
    return a;
}
static __device__ __forceinline__ uint32_t cvt_tf32(float v) {
    uint32_t t;
    asm("cvt.rna.tf32.f32 %0, %1;" : "=r"(t) : "f"(v));
    return t;
}
static __device__ __forceinline__ void sts_v2(int addr, uint32_t lo, uint32_t hi) {
    asm volatile("st.shared.v2.b32 [%0], {%1, %2};" :: "r"(addr), "r"(lo), "r"(hi));
}
static __device__ __forceinline__ void sts_b32(int addr, uint32_t v) {
    asm volatile("st.shared.b32 [%0], %1;" :: "r"(addr), "r"(v));
}
static __device__ __forceinline__ void mma4(float* a, uint32_t a0, uint32_t a1,
                                            uint32_t a2, uint32_t a3, uint2 bv) {
    asm volatile(
        "mma.sync.aligned.m16n8k8.row.col.f32.tf32.tf32.f32 "
        "{%0,%1,%2,%3}, {%4,%5,%6,%7}, {%8,%9}, {%0,%1,%2,%3};"
        : "+f"(a[0]), "+f"(a[1]), "+f"(a[2]), "+f"(a[3])
        : "r"(a0), "r"(a1), "r"(a2), "r"(a3), "r"(bv.x), "r"(bv.y));
}

static __device__ __forceinline__ int xword(int r, int c) {
    int kt = c >> 2, rho = kt & 3;
    return (r >> 4) * 1536 + kt * 128 + (((r & 7) ^ ((r >> 1) & 1)) << 4)
         + (((c & 3) ^ ((r >> 1) & 3)) << 2) + ((((r >> 3) & 1) << 1) ^ (rho & 2));
}
static __device__ __forceinline__ int dword_(int r, int c) {
    int kt = 8 + (c >> 3), rho = kt & 3, khigh = (c >> 2) & 1;
    return (r >> 4) * 1536 + kt * 128 + (((r & 7) ^ ((r >> 1) & 1)) << 4)
         + (((c & 3) ^ ((r >> 1) & 3)) << 2) + (((((r >> 3) & 1) << 1) | khigh) ^ rho);
}

#define SEL(i, R) (((((i) & 1) << 1) | ((i) >> 1)) ^ (R))

__global__ void __launch_bounds__(THREADS, 2)
dijet_mma(const float* __restrict__ x, const float* __restrict__ dd,
          const float* __restrict__ bvec, float* __restrict__ out, int nsamp)
{
    extern __shared__ char smem[];
    const uint32_t sb = smem_u32(smem);
    const int tid = threadIdx.x;
    const int wid = tid >> 5, lane = tid & 31;
    const int g8 = lane >> 2, t4 = lane & 3;
    const int ntiles = (nsamp + 15) >> 4;
    const int tstep = gridDim.x;
    int t = blockIdx.x;
    if (t >= ntiles) return;

    // ---- B image -> smem (once per CTA) ----
    {
        const float4* wf4 = (const float4*)WF_g;
        float4* b4 = (float4*)(smem + B_OFF);
        #pragma unroll
        for (int i = tid; i < B_BYTES / 16; i += THREADS) b4[i] = wf4[i];
    }

    // ---- role state (set up ONCE; advances by constants thereafter) ----
    float2 bias[4];
    int ax[4], bxx[4]; bool swx = false;
    int ad[16];
    int gq = 0, nb = 0;
    if (wid < 3) {
        const float2* b2 = (const float2*)bvec;
        #pragma unroll
        for (int nt = 0; nt < 4; nt++) bias[nt] = b2[nt * 4 + t4];
    } else if (wid < 6) {          // d-producers: 96 threads, 8 f4/tile each
        int ptid = tid - 96;
        int i0g = ptid / 48, rem = ptid - 48 * i0g;
        #pragma unroll
        for (int os = 0; os < 4; os++)
            #pragma unroll
            for (int e = 0; e < 4; e++) {
                int f = 4 * rem + e;
                int c = f / 6, s = f - 6 * c;
                ad[os * 4 + e] = (int)sb + 4 * dword_(6 * (i0g + 2 * os) + s, c);
            }
        gq = (t * 16 + i0g) * 48 + rem;
        nb = t * 16 + i0g;
    } else {                        // x-producers: 192 threads, 8 f4/tile each
        int ptid = tid - 192;
        int i0g = ptid / 96, rem = ptid - 96 * i0g;
        int c = rem / 3, qq = rem - 3 * c;
        swx = (c >> 2) & 1;
        #pragma unroll
        for (int os = 0; os < 4; os++) {
            int rA = 6 * (i0g + 2 * os) + 2 * qq;
            ax[os]  = (int)sb + 4 * xword(rA, c);
            bxx[os] = (int)sb + 4 * xword(rA + 1, c);
        }
        gq = (t * 16 + i0g) * 96 + rem;
        nb = t * 16 + i0g;
    }

    auto stage_x = [&]() {
        const float4* x4 = (const float4*)x;
        #pragma unroll
        for (int st = 0; st < 2; st++)
            #pragma unroll
            for (int os = 0; os < 4; os++) {
                if (nb + 2 * os + 8 * st < nsamp) {
                    float4 v = x4[gq + os * 192 + st * 768];
                    uint32_t e0 = cvt_tf32(v.x), e1 = cvt_tf32(v.y);
                    uint32_t e2 = cvt_tf32(v.z), e3 = cvt_tf32(v.w);
                    int aA = ax[os] + st * 18432, aB = bxx[os] + st * 18432;
                    if (swx) { sts_v2(aA, e1, e0); sts_v2(aB, e3, e2); }
                    else     { sts_v2(aA, e0, e1); sts_v2(aB, e2, e3); }
                }
            }
    };
    auto stage_d = [&]() {
        const float4* d4 = (const float4*)dd;
        #pragma unroll
        for (int st = 0; st < 2; st++)
            #pragma unroll
            for (int os = 0; os < 4; os++) {
                if (nb + 2 * os + 8 * st < nsamp) {
                    float4 v = d4[gq + os * 96 + st * 384];
                    int o4 = st * 18432;
                    sts_b32(ad[os * 4 + 0] + o4, cvt_tf32(v.x));
                    sts_b32(ad[os * 4 + 1] + o4, cvt_tf32(v.y));
                    sts_b32(ad[os * 4 + 2] + o4, cvt_tf32(v.z));
                    sts_b32(ad[os * 4 + 3] + o4, cvt_tf32(v.w));
                }
            }
    };
    auto adv_x = [&](int db) {
        #pragma unroll
        for (int os = 0; os < 4; os++) { ax[os] += db; bxx[os] += db; }
        gq += tstep * 1536; nb += tstep * 16;
    };
    auto adv_d = [&](int db) {
        #pragma unroll
        for (int e = 0; e < 16; e++) ad[e] += db;
        gq += tstep * 768; nb += tstep * 16;
    };

    // ---- prologue: stage tile t into buf0, point producers at buf1 ----
    if (wid >= 6)      { stage_x(); adv_x(ABUF); }
    else if (wid >= 3) { stage_d(); adv_d(ABUF); }
    int dA = -ABUF;
    int p = 0;

    for (;;) {
        int tn = t + tstep;
        float acc0[4][4], acc1[4][4];
        __syncthreads();   // buf[p] ready; buf[1-p] free (copied out / fresh)

        if (wid >= 6) {
            if (tn < ntiles) { stage_x(); adv_x(dA); dA = -dA; }
        } else if (wid >= 3) {
            if (tn < ntiles) { stage_d(); adv_d(dA); dA = -dA; }
        } else {
            #pragma unroll
            for (int nt = 0; nt < 4; nt++) {
                acc0[nt][0] = bias[nt].x; acc0[nt][1] = bias[nt].y;
                acc0[nt][2] = bias[nt].x; acc0[nt][3] = bias[nt].y;
                acc1[nt][0] = bias[nt].x; acc1[nt][1] = bias[nt].y;
                acc1[nt][2] = bias[nt].x; acc1[nt][3] = bias[nt].y;
            }
            const int aoff = ((g8 ^ ((g8 >> 1) & 1)) << 6) + ((t4 ^ ((g8 >> 1) & 3)) << 4);
            const char* a0base = smem + p * ABUF + (2 * wid) * 6144 + aoff;
            const char* a1base = a0base + 6144;
            const char* bbase  = smem + B_OFF + lane * 8;

#define KSTEP(KT, RHO) { \
            uint4 av0 = *(const uint4*)(a0base + (KT) * 512); \
            uint4 av1 = *(const uint4*)(a1base + (KT) * 512); \
            uint32_t p0[4] = {av0.x, av0.y, av0.z, av0.w}; \
            uint32_t p1[4] = {av1.x, av1.y, av1.z, av1.w}; \
            _Pragma("unroll") \
            for (int nt = 0; nt < 4; nt++) { \
                uint2 bv = *(const uint2*)(bbase + ((KT) * 4 + nt) * 256); \
                mma4(acc0[nt], p0[SEL(0,RHO)], p0[SEL(1,RHO)], p0[SEL(2,RHO)], p0[SEL(3,RHO)], bv); \
                mma4(acc1[nt], p1[SEL(0,RHO)], p1[SEL(1,RHO)], p1[SEL(2,RHO)], p1[SEL(3,RHO)], bv); \
            } }

            KSTEP(0, 0) KSTEP(1, 1) KSTEP(2, 2) KSTEP(3, 3)
            KSTEP(4, 0) KSTEP(5, 1) KSTEP(6, 2) KSTEP(7, 3)
            KSTEP(8, 0) KSTEP(9, 1) KSTEP(10, 2) KSTEP(11, 3)
#undef KSTEP
        }

        __syncthreads();   // consumers done reading buf[p]; producers done staging buf[1-p]

        if (wid < 3) {     // scatter accs into buf[p] (now free), stride-200 rows
            float* ep = (float*)(smem + p * ABUF);
            #pragma unroll
            for (int mt = 0; mt < 2; mt++) {
                const float (*ac)[4] = mt ? acc1 : acc0;
                #pragma unroll
                for (int h = 0; h < 2; h++) {
                    int r = (2 * wid + mt) * 16 + g8 + 8 * h;
                    int i = r / 6, s = r - 6 * i;
                    int base = i * EPI_STRIDE + s;
                    #pragma unroll
                    for (int nt = 0; nt < 4; nt++) {
                        int o = nt * 8 + 2 * t4;
                        ep[base + o * 6]       = ac[nt][2 * h];
                        ep[base + (o + 1) * 6] = ac[nt][2 * h + 1];
                    }
                }
            }
        }
        __syncthreads();

        {   // coalesced copy-out of tile t (all 12 warps)
            const int i0 = tid / 48;
            const int m0 = (tid - 48 * i0) * 4;
            const float* ep = (const float*)(smem + p * ABUF) + i0 * EPI_STRIDE + m0;
            float* ob = out + (size_t)t * 3072 + tid * 4;
            int limit = (nsamp - t * 16) * 192;
            #pragma unroll
            for (int it = 0; it < 2; it++) {
                if (tid * 4 + it * 1536 < limit) {
                    float4 v = *(const float4*)(ep + it * (8 * EPI_STRIDE));
                    *(float4*)(ob + it * 1536) = v;
                }
            }
        }

        if (tn >= ntiles) break;
        t = tn; p ^= 1;
    }
}

extern "C" void kernel_launch(void* const* d_in, const int* in_sizes, int n_in,
                              void* d_out, int out_size) {
    const float* x = (const float*)d_in[0];
    const float* d = (const float*)d_in[1];
    const float* W = (const float*)d_in[2];
    const float* b = (const float*)d_in[3];
    float* out = (float*)d_out;

    int nsamp = in_sizes[0] / 384;
    int ntiles = (nsamp + 15) / 16;
    int nblk = ntiles < NCTA ? ntiles : NCTA;

    cudaFuncSetAttribute(dijet_mma, cudaFuncAttributeMaxDynamicSharedMemorySize, SMEM_TOTAL);
    prep_WF<<<24, 128>>>(W);
    dijet_mma<<<nblk, THREADS, SMEM_TOTAL>>>(x, d, b, out, nsamp);
}

// round 17
// speedup vs baseline: 1.7859x; 1.7859x over previous
#include <cuda_runtime.h>
#include <cstdint>

// out[n,o,s] = sum_k din[j,k] * W[o,k] + b[o],  j = n*6+s, K=96 (k = 3c+tap)
// mma.sync.m16n8k8.row.col.f32.tf32.tf32.f32 (plain PTX, compute_103-safe).
//
// A layout (R10), value (row r, kt, t), t&3 = c&3, khigh = t>>2, rho = kt&3:
//   word = (r>>4)*1536 + kt*128 + (((r&7) ^ ((r>>1)&1))<<4)
//        + (((c&3) ^ ((r>>1)&3))<<2) + ((((r>>3)&1)<<1 | khigh) ^ rho')
// x-taps: kt=c>>2, khigh=par, rho' = rho&2 (pairs in natural par order -> 8B cp.async;
//         consumer compensates with RHO = kt&2).  d-tap: kt=8+(c>>3), rho' = rho (unchanged).
// W packed into smem B region INSIDE the kernel (no prep launch). x staged via
// cp.async raw fp32 (HMMA reads tf32 bits); d and W tf32-rounded (rna).

#define ROWS 192
#define THREADS 384
#define A_BYTES 73728
#define B_OFF A_BYTES
#define B_BYTES 12288
#define SMEM_TOTAL (A_BYTES + B_BYTES)     // 86016 -> 2 CTAs/SM
#define EPI_STRIDE 200

static __device__ __forceinline__ uint32_t smem_u32(const void* p) {
    uint32_t a;
    asm("{ .reg .u64 t; cvta.to.shared.u64 t, %1; cvt.u32.u64 %0, t; }" : "=r"(a) : "l"(p));
    return a;
}
static __device__ __forceinline__ uint32_t cvt_tf32(float v) {
    uint32_t t;
    asm("cvt.rna.tf32.f32 %0, %1;" : "=r"(t) : "f"(v));
    return t;
}
static __device__ __forceinline__ void sts_b32(int addr, uint32_t v) {
    asm volatile("st.shared.b32 [%0], %1;" :: "r"(addr), "r"(v));
}
static __device__ __forceinline__ void cp8(int dst, const char* gsrc) {
    asm volatile("cp.async.ca.shared.global [%0], [%1], 8;"
                 :: "r"((uint32_t)dst), "l"(gsrc) : "memory");
}
static __device__ __forceinline__ void cp_commit_wait() {
    asm volatile("cp.async.commit_group;" ::: "memory");
    asm volatile("cp.async.wait_group 0;" ::: "memory");
}
static __device__ __forceinline__ void mma4(float* a, uint32_t a0, uint32_t a1,
                                            uint32_t a2, uint32_t a3, uint2 bv) {
    asm volatile(
        "mma.sync.aligned.m16n8k8.row.col.f32.tf32.tf32.f32 "
        "{%0,%1,%2,%3}, {%4,%5,%6,%7}, {%8,%9}, {%0,%1,%2,%3};"
        : "+f"(a[0]), "+f"(a[1]), "+f"(a[2]), "+f"(a[3])
        : "r"(a0), "r"(a1), "r"(a2), "r"(a3), "r"(bv.x), "r"(bv.y));
}

// x pair-base word: parity pair at {word, word+1}, natural par order (rho&2 only)
static __device__ __forceinline__ int xword(int r, int c) {
    int kt = c >> 2, rho = kt & 3;
    return (r >> 4) * 1536 + kt * 128 + (((r & 7) ^ ((r >> 1) & 1)) << 4)
         + (((c & 3) ^ ((r >> 1) & 3)) << 2) + ((((r >> 3) & 1) << 1) ^ (rho & 2));
}
static __device__ __forceinline__ int dword_(int r, int c) {
    int kt = 8 + (c >> 3), rho = kt & 3, khigh = (c >> 2) & 1;
    return (r >> 4) * 1536 + kt * 128 + (((r & 7) ^ ((r >> 1) & 1)) << 4)
         + (((c & 3) ^ ((r >> 1) & 3)) << 2) + (((((r >> 3) & 1) << 1) | khigh) ^ rho);
}

#define SEL(i, R) (((((i) & 1) << 1) | ((i) >> 1)) ^ (R))

__global__ void __launch_bounds__(THREADS, 2)
dijet_mma(const float* __restrict__ x, const float* __restrict__ dd,
          const float* __restrict__ W, const float* __restrict__ bvec,
          float* __restrict__ out, int nsamp)
{
    extern __shared__ char smem[];
    const uint32_t sb = smem_u32(smem);
    const int tid = threadIdx.x;
    const int j0  = blockIdx.x * ROWS;
    const int n0  = j0 / 6;
    const bool full = (nsamp - n0) >= 32;

    // ---- x staging: fire-and-forget 8B cp.async (raw fp32; HMMA reads tf32 bits) ----
    {
        const int i0  = tid / 96;
        const int rem = tid - 96 * i0;
        const int c   = rem / 3, qq = rem - 3 * c;
        const int rA  = 6 * i0 + 2 * qq;
        int aA0 = (int)sb + 4 * xword(rA,      c);
        int aB0 = (int)sb + 4 * xword(rA + 1,  c);
        int aA1 = (int)sb + 4 * xword(rA + 24, c);
        int aB1 = (int)sb + 4 * xword(rA + 25, c);
        const char* xb = (const char*)x;
        int64_t g = ((int64_t)(n0 + i0) * 96 + rem) * 16;
        int n = n0 + i0;
        #pragma unroll
        for (int ds = 0; ds < 4; ds++) {
            if (full || n < nsamp) {
                cp8(aA0, xb + g);
                cp8(aB0, xb + g + 8);
            }
            if (full || n + 4 < nsamp) {
                cp8(aA1, xb + g + 6144);
                cp8(aB1, xb + g + 6144 + 8);
            }
            g += 12288; n += 8;
            aA0 += 18432; aB0 += 18432; aA1 += 18432; aB1 += 18432;
        }
    }

    // ---- W fragment-pack into smem B region (8 elems/thread, rna-rounded) ----
    {
        const int o  = tid / 12;
        const int kb = (tid - 12 * o) * 8;
        const float4* w4 = (const float4*)(W + o * 96 + kb);
        float4 wa = w4[0], wb = w4[1];
        float wv[8] = {wa.x, wa.y, wa.z, wa.w, wb.x, wb.y, wb.z, wb.w};
        #pragma unroll
        for (int e = 0; e < 8; e++) {
            int k = kb + e;
            int c = k / 3, tap = k - 3 * c;
            int kt, tc;
            if (tap < 2) { kt = c >> 2;       tc = (c & 3) + 4 * tap; }
            else         { kt = 8 + (c >> 3); tc = c & 7; }
            int word = (kt * 4 + (o >> 3)) * 64 + ((o & 7) * 4 + (tc & 3)) * 2 + (tc >> 2);
            sts_b32((int)sb + B_OFF + 4 * word, cvt_tf32(wv[e]));
        }
    }

    // ---- d staging: LDG + rna cvt + STS (flies under the x cp.asyncs) ----
    {
        const int i0  = tid / 48;
        const int rem = tid - 48 * i0;
        int addr[4];
        #pragma unroll
        for (int e = 0; e < 4; e++) {
            int f = 4 * rem + e;
            int c = f / 6, s = f - 6 * c;
            addr[e] = (int)sb + 4 * dword_(6 * i0 + s, c);
        }
        const float4* d4 = (const float4*)dd;
        int g = (n0 + i0) * 48 + rem;
        int n = n0 + i0;
        #pragma unroll
        for (int st = 0; st < 4; st++) {
            if (full || n < nsamp) {
                float4 v = d4[g];
                sts_b32(addr[0], cvt_tf32(v.x)); sts_b32(addr[1], cvt_tf32(v.y));
                sts_b32(addr[2], cvt_tf32(v.z)); sts_b32(addr[3], cvt_tf32(v.w));
            }
            g += 384; n += 8;
            #pragma unroll
            for (int e = 0; e < 4; e++) addr[e] += 18432;
        }
    }

    cp_commit_wait();
    __syncthreads();

    const int wid = tid >> 5, lane = tid & 31;
    const int g8 = lane >> 2, t4 = lane & 3;

    float acc0[4][4], acc1[4][4];

    if (wid < 6) {
        const float2* b2 = (const float2*)bvec;
        #pragma unroll
        for (int nt = 0; nt < 4; nt++) {
            float2 bb = b2[nt * 4 + t4];
            acc0[nt][0] = bb.x; acc0[nt][1] = bb.y; acc0[nt][2] = bb.x; acc0[nt][3] = bb.y;
            acc1[nt][0] = bb.x; acc1[nt][1] = bb.y; acc1[nt][2] = bb.x; acc1[nt][3] = bb.y;
        }
        const int aoff = ((g8 ^ ((g8 >> 1) & 1)) << 6) + ((t4 ^ ((g8 >> 1) & 3)) << 4);
        const char* a0base = smem + (2 * wid)     * 6144 + aoff;
        const char* a1base = smem + (2 * wid + 1) * 6144 + aoff;
        const char* bbase  = smem + B_OFF + lane * 8;

#define KSTEP(KT, RHO) { \
        uint4 av0 = *(const uint4*)(a0base + (KT) * 512); \
        uint4 av1 = *(const uint4*)(a1base + (KT) * 512); \
        uint32_t p0[4] = {av0.x, av0.y, av0.z, av0.w}; \
        uint32_t p1[4] = {av1.x, av1.y, av1.z, av1.w}; \
        _Pragma("unroll") \
        for (int nt = 0; nt < 4; nt++) { \
            uint2 bv = *(const uint2*)(bbase + ((KT) * 4 + nt) * 256); \
            mma4(acc0[nt], p0[SEL(0,RHO)], p0[SEL(1,RHO)], p0[SEL(2,RHO)], p0[SEL(3,RHO)], bv); \
            mma4(acc1[nt], p1[SEL(0,RHO)], p1[SEL(1,RHO)], p1[SEL(2,RHO)], p1[SEL(3,RHO)], bv); \
        } }

        // x K-steps: layout uses rho&2 only -> RHO = kt&2
        KSTEP(0, 0) KSTEP(1, 0) KSTEP(2, 2) KSTEP(3, 2)
        KSTEP(4, 0) KSTEP(5, 0) KSTEP(6, 2) KSTEP(7, 2)
        // d K-steps: full rho
        KSTEP(8, 0) KSTEP(9, 1) KSTEP(10, 2) KSTEP(11, 3)
#undef KSTEP
    }

    // ---- epilogue: scatter to smem (stride-200), then coalesced copy-out ----
    __syncthreads();
    if (wid < 6) {
        float* ep = (float*)smem;
        #pragma unroll
        for (int mt = 0; mt < 2; mt++) {
            const float (*ac)[4] = mt ? acc1 : acc0;
            #pragma unroll
            for (int h = 0; h < 2; h++) {
                int r = (2 * wid + mt) * 16 + g8 + 8 * h;
                int i = r / 6, s = r - 6 * i;
                int base = i * EPI_STRIDE + s;
                #pragma unroll
                for (int nt = 0; nt < 4; nt++) {
                    int o = nt * 8 + 2 * t4;
                    ep[base + o * 6]       = ac[nt][2 * h];
                    ep[base + (o + 1) * 6] = ac[nt][2 * h + 1];
                }
            }
        }
    }
    __syncthreads();
    {
        const int i0 = tid / 48;
        const int m0 = (tid - 48 * i0) * 4;
        const float* ep = (const float*)smem + i0 * EPI_STRIDE + m0;
        float* ob = out + (size_t)n0 * 192 + tid * 4;
        if (full) {
            #pragma unroll
            for (int it = 0; it < 4; it++) {
                float4 v = *(const float4*)(ep + it * (8 * EPI_STRIDE));
                *(float4*)(ob + it * 1536) = v;
            }
        } else {
            int limit = (nsamp - n0) * 192;
            #pragma unroll
            for (int it = 0; it < 4; it++) {
                if (tid * 4 + it * 1536 < limit) {
                    float4 v = *(const float4*)(ep + it * (8 * EPI_STRIDE));
                    *(float4*)(ob + it * 1536) = v;
                }
            }
        }
    }
}

extern "C" void kernel_launch(void* const* d_in, const int* in_sizes, int n_in,
                              void* d_out, int out_size) {
    const float* x = (const float*)d_in[0];
    const float* d = (const float*)d_in[1];
    const float* W = (const float*)d_in[2];
    const float* b = (const float*)d_in[3];
    float* out = (float*)d_out;

    int nsamp = in_sizes[0] / 384;

    cudaFuncSetAttribute(dijet_mma, cudaFuncAttributeMaxDynamicSharedMemorySize, SMEM_TOTAL);
    int nblk = (nsamp * 6 + ROWS - 1) / ROWS;
    dijet_mma<<<nblk, THREADS, SMEM_TOTAL>>>(x, d, W, b, out, nsamp);
}